// round 1
// baseline (speedup 1.0000x reference)
#include <cuda_runtime.h>

#define NB   64
#define ND   2048
#define NE   64
#define NH1  512
#define NH2  256
#define EPSB 1e-5f

// Scratch (allocation-free): precomputed per-call
__device__ float g_base[NB * NH1];   // rep @ W1d + b1
__device__ float g_embh[ND * NH1];   // emb @ W1e
__device__ float g_c1[NH1], g_c0[NH1];        // folded BN1
__device__ float g_e1[NH2], g_e0[NH2], g_w3[NH2]; // folded BN2 (+b2) and W3

// ---------- packed f32x2 helpers (Blackwell FFMA2) ----------
__device__ __forceinline__ unsigned long long pack2same(float x) {
    unsigned long long r;
    asm("mov.b64 %0, {%1, %1};" : "=l"(r) : "f"(x));
    return r;
}
__device__ __forceinline__ unsigned long long ffma2(unsigned long long a,
                                                    unsigned long long b,
                                                    unsigned long long c) {
    unsigned long long d;
    asm("fma.rn.f32x2 %0, %1, %2, %3;" : "=l"(d) : "l"(a), "l"(b), "l"(c));
    return d;
}
__device__ __forceinline__ float2 unpack2(unsigned long long v) {
    float2 f;
    asm("mov.b64 {%0, %1}, %2;" : "=f"(f.x), "=f"(f.y) : "l"(v));
    return f;
}

// ---------- prep: fold BN constants ----------
__global__ void prep_consts(const float* __restrict__ g1, const float* __restrict__ beta1,
                            const float* __restrict__ m1, const float* __restrict__ v1,
                            const float* __restrict__ b2, const float* __restrict__ g2,
                            const float* __restrict__ beta2, const float* __restrict__ m2,
                            const float* __restrict__ v2, const float* __restrict__ W3) {
    int t = threadIdx.x;
    if (t < NH1) {
        float c1 = g1[t] * rsqrtf(v1[t] + EPSB);
        g_c1[t] = c1;
        g_c0[t] = beta1[t] - m1[t] * c1;
    }
    if (t < NH2) {
        float e1 = g2[t] * rsqrtf(v2[t] + EPSB);
        g_e1[t] = e1;
        g_e0[t] = (b2[t] - m2[t]) * e1 + beta2[t];
        g_w3[t] = W3[t];
    }
}

// ---------- prep: base[b,h] = b1[h] + sum_d rep[b,d] * W1[d,h] ----------
__global__ __launch_bounds__(512) void prep_base(const float* __restrict__ rep,
                                                 const float* __restrict__ W1,
                                                 const float* __restrict__ b1) {
    __shared__ float reps[ND];
    int b = blockIdx.x;
    for (int i = threadIdx.x; i < ND; i += 512) reps[i] = rep[(size_t)b * ND + i];
    __syncthreads();
    int h = threadIdx.x;  // 0..511
    float acc = b1[h];
#pragma unroll 8
    for (int d = 0; d < ND; d++)
        acc = fmaf(reps[d], W1[(size_t)d * NH1 + h], acc);
    g_base[(size_t)b * NH1 + h] = acc;
}

// ---------- prep: emb_h[k,h] = sum_e emb[k,e] * W1[D+e,h] ----------
__global__ __launch_bounds__(512) void prep_embh(const float* __restrict__ emb,
                                                 const float* __restrict__ W1) {
    __shared__ float es[8 * NE];
    int kb = blockIdx.x * 8;
    for (int i = threadIdx.x; i < 8 * NE; i += 512) es[i] = emb[(size_t)kb * NE + i];
    __syncthreads();
    int h = threadIdx.x;
    const float* W1e = W1 + (size_t)ND * NH1;
    float acc[8];
#pragma unroll
    for (int kr = 0; kr < 8; kr++) acc[kr] = 0.f;
#pragma unroll 4
    for (int e = 0; e < NE; e++) {
        float w = W1e[(size_t)e * NH1 + h];
#pragma unroll
        for (int kr = 0; kr < 8; kr++) acc[kr] = fmaf(es[kr * NE + e], w, acc[kr]);
    }
#pragma unroll
    for (int kr = 0; kr < 8; kr++) g_embh[(size_t)(kb + kr) * NH1 + h] = acc[kr];
}

// ---------- main fused kernel ----------
// Grid: (D/64, B). Block: 256 threads (8 warps).
// CTA tile: M=64 k-rows, N=256 outputs (all of H2), K=H1=512 in chunks of 32.
// warp = row-group (8 rows each), lane = col-group (8 cols each).
__global__ __launch_bounds__(256, 2) void fused_main(
    const float* __restrict__ rep, const float* __restrict__ W1,
    const float* __restrict__ W2, const float* __restrict__ b3,
    float* __restrict__ out)
{
    __shared__ __align__(16) float As[32 * 65];    // h1f chunk, [kk][k], pad 65
    __shared__ __align__(16) float Bs[32 * 256];   // W2 chunk, [kk][o]
    __shared__ float reps[64];

    const int b  = blockIdx.y;
    const int k0 = blockIdx.x * 64;
    const int t  = threadIdx.x;
    const int warp = t >> 5, lane = t & 31;

    if (t < 64) reps[t] = rep[(size_t)b * ND + k0 + t];
    __syncthreads();

    unsigned long long acc[8][4];
#pragma unroll
    for (int i = 0; i < 8; i++)
#pragma unroll
        for (int j = 0; j < 4; j++) acc[i][j] = 0ULL;  // (0.f, 0.f)

    const float* baseb = g_base + (size_t)b * NH1;

#pragma unroll 1
    for (int h0 = 0; h0 < NH1; h0 += 32) {
        // -------- stage A: build h1f chunk into As (transposed, [hl][k]) --------
#pragma unroll
        for (int r = 0; r < 2; r++) {
            int idx = t + r * 256;         // 0..511
            int k   = idx >> 3;            // 0..63
            int c4  = (idx & 7) << 2;      // 0,4,..,28
            int h   = h0 + c4;
            float4 wv  = *(const float4*)(W1 + (size_t)(k0 + k) * NH1 + h);
            float4 ev  = *(const float4*)(g_embh + (size_t)(k0 + k) * NH1 + h);
            float4 bb  = *(const float4*)(baseb + h);
            float4 c1v = *(const float4*)(g_c1 + h);
            float4 c0v = *(const float4*)(g_c0 + h);
            float rp = reps[k];
            float u;
            u = bb.x + ev.x - rp * wv.x;
            As[(c4 + 0) * 65 + k] = fmaxf(fmaf(u, c1v.x, c0v.x), 0.f);
            u = bb.y + ev.y - rp * wv.y;
            As[(c4 + 1) * 65 + k] = fmaxf(fmaf(u, c1v.y, c0v.y), 0.f);
            u = bb.z + ev.z - rp * wv.z;
            As[(c4 + 2) * 65 + k] = fmaxf(fmaf(u, c1v.z, c0v.z), 0.f);
            u = bb.w + ev.w - rp * wv.w;
            As[(c4 + 3) * 65 + k] = fmaxf(fmaf(u, c1v.w, c0v.w), 0.f);
        }
        // -------- load W2 chunk into Bs --------
#pragma unroll
        for (int r = 0; r < 8; r++) {
            int idx = t + r * 256;         // 0..2047
            int row = idx >> 6;            // 0..31
            int c   = (idx & 63) << 2;     // 0..252
            *(float4*)(Bs + row * 256 + c) =
                *(const float4*)(W2 + (size_t)(h0 + row) * NH2 + c);
        }
        __syncthreads();

        // -------- stage B: 64x256x32 microkernel with packed FFMA2 --------
#pragma unroll 8
        for (int kk = 0; kk < 32; kk++) {
            unsigned long long bp[4];
            {
                ulonglong2 q0 = *(const ulonglong2*)(Bs + kk * 256 + lane * 8);
                ulonglong2 q1 = *(const ulonglong2*)(Bs + kk * 256 + lane * 8 + 4);
                bp[0] = q0.x; bp[1] = q0.y; bp[2] = q1.x; bp[3] = q1.y;
            }
            const float* arow = As + kk * 65 + warp * 8;
#pragma unroll
            for (int i = 0; i < 8; i++) {
                unsigned long long ap = pack2same(arow[i]);
#pragma unroll
                for (int j = 0; j < 4; j++) acc[i][j] = ffma2(ap, bp[j], acc[i][j]);
            }
        }
        __syncthreads();
    }

    // -------- epilogue: BN2+relu, dot with W3, warp-reduce over o --------
    const int o0 = lane * 8;
    float e1v[8], e0v[8], w3v[8];
#pragma unroll
    for (int j = 0; j < 8; j++) {
        e1v[j] = g_e1[o0 + j];
        e0v[j] = g_e0[o0 + j];
        w3v[j] = g_w3[o0 + j];
    }
    const float bias3 = b3[0];

#pragma unroll
    for (int i = 0; i < 8; i++) {
        float s = 0.f;
#pragma unroll
        for (int j2 = 0; j2 < 4; j2++) {
            float2 v = unpack2(acc[i][j2]);
            float ha = fmaxf(fmaf(v.x, e1v[j2 * 2 + 0], e0v[j2 * 2 + 0]), 0.f);
            float hb = fmaxf(fmaf(v.y, e1v[j2 * 2 + 1], e0v[j2 * 2 + 1]), 0.f);
            s = fmaf(ha, w3v[j2 * 2 + 0], s);
            s = fmaf(hb, w3v[j2 * 2 + 1], s);
        }
#pragma unroll
        for (int off = 16; off; off >>= 1) s += __shfl_xor_sync(0xffffffffu, s, off);
        if (lane == 0) out[(size_t)b * ND + k0 + warp * 8 + i] = s + bias3;
    }
}

extern "C" void kernel_launch(void* const* d_in, const int* in_sizes, int n_in,
                              void* d_out, int out_size) {
    const float* rep   = (const float*)d_in[0];
    const float* emb   = (const float*)d_in[1];
    const float* W1    = (const float*)d_in[2];
    const float* b1    = (const float*)d_in[3];
    const float* g1    = (const float*)d_in[4];
    const float* beta1 = (const float*)d_in[5];
    const float* m1    = (const float*)d_in[6];
    const float* v1    = (const float*)d_in[7];
    const float* W2    = (const float*)d_in[8];
    const float* b2    = (const float*)d_in[9];
    const float* g2    = (const float*)d_in[10];
    const float* beta2 = (const float*)d_in[11];
    const float* m2    = (const float*)d_in[12];
    const float* v2    = (const float*)d_in[13];
    const float* W3    = (const float*)d_in[14];
    const float* b3    = (const float*)d_in[15];
    float* out = (float*)d_out;

    prep_consts<<<1, 512>>>(g1, beta1, m1, v1, b2, g2, beta2, m2, v2, W3);
    prep_base<<<NB, 512>>>(rep, W1, b1);
    prep_embh<<<ND / 8, 512>>>(emb, W1);
    dim3 grid(ND / 64, NB);
    fused_main<<<grid, 256>>>(rep, W1, W2, b3, out);
}